// round 16
// baseline (speedup 1.0000x reference)
#include <cuda_runtime.h>

// out[b, n] = sum_e c[b, n, e] * s[b, e]
//   B=32, N=8192, E=256 (fp32).  HBM-bound: 256 MB streamed once.
//
// R15 -> R16: CTA-size knob. R11/R12/R15 all plateau at 41.47us with
// 256-thread CTAs; persistence and quantum size are exhausted. This keeps
// the best-measured load shape (R12: 2 rows/warp, MLP=4, no loop) but in
// 128-thread CTAs (4 warps): 16 CTAs/SM resident, halved scheduler refill
// quantum, smoother per-SM warp population through block churn.
//   grid 32768 x 128thr, 8 rows/CTA. No smem, no sync.

static constexpr int B = 32;
static constexpr int N = 8192;              // rows per batch
static constexpr int E4 = 64;               // 256 floats = 64 float4 per row
static constexpr int WARPS_PER_BLOCK = 4;
static constexpr int THREADS = WARPS_PER_BLOCK * 32;        // 128
static constexpr int ROWS_PER_WARP = 2;
static constexpr int ROWS_PER_BLOCK = WARPS_PER_BLOCK * ROWS_PER_WARP;  // 8
static constexpr int TOTAL_ROWS = B * N;                    // 262144
static constexpr int NUM_BLOCKS = TOTAL_ROWS / ROWS_PER_BLOCK;  // 32768

__device__ __forceinline__ float dot8(float4 a0, float4 a1, float4 w0, float4 w1)
{
    float s = a0.x * w0.x;
    s = fmaf(a0.y, w0.y, s);
    s = fmaf(a0.z, w0.z, s);
    s = fmaf(a0.w, w0.w, s);
    s = fmaf(a1.x, w1.x, s);
    s = fmaf(a1.y, w1.y, s);
    s = fmaf(a1.z, w1.z, s);
    s = fmaf(a1.w, w1.w, s);
    return s;
}

__device__ __forceinline__ float warp_reduce(float v)
{
    #pragma unroll
    for (int off = 16; off > 0; off >>= 1)
        v += __shfl_xor_sync(0xFFFFFFFFu, v, off);
    return v;
}

__global__ __launch_bounds__(THREADS)
void css_dot_kernel(const float4* __restrict__ c,
                    const float4* __restrict__ s,
                    float* __restrict__ out)
{
    const int warp = threadIdx.x >> 5;
    const int lane = threadIdx.x & 31;
    const int row0 = blockIdx.x * ROWS_PER_BLOCK + warp * ROWS_PER_WARP;
    const int b    = row0 >> 13;                            // row0 / N

    const float4* __restrict__ rA = c + (size_t)row0 * E4;

    // 4 independent 128-bit streaming loads per lane (MLP=4).
    float4 a0 = __ldcs(rA + lane);
    float4 a1 = __ldcs(rA + lane + 32);
    float4 b0 = __ldcs(rA + lane + 64);
    float4 b1 = __ldcs(rA + lane + 96);

    // Weights for this batch (L1-hot broadcast; overlapped with LDGs above).
    const float4* __restrict__ sw = s + b * E4 + lane;
    float4 w0 = sw[0];
    float4 w1 = sw[32];

    float sumA = warp_reduce(dot8(a0, a1, w0, w1));
    float sumB = warp_reduce(dot8(b0, b1, w0, w1));

    // Adjacent output rows -> one 64-bit store from lane 0.
    if (lane == 0) {
        float2 r; r.x = sumA; r.y = sumB;
        *reinterpret_cast<float2*>(out + row0) = r;
    }
}

extern "C" void kernel_launch(void* const* d_in, const int* in_sizes, int n_in,
                              void* d_out, int out_size)
{
    (void)in_sizes; (void)n_in; (void)out_size;
    const float4* c = (const float4*)d_in[0];
    const float4* s = (const float4*)d_in[1];
    float* out = (float*)d_out;

    css_dot_kernel<<<NUM_BLOCKS, THREADS>>>(c, s, out);
}